// round 1
// baseline (speedup 1.0000x reference)
#include <cuda_runtime.h>
#include <math.h>

// GRU: B=128, T=512, I=256, H=512. out = final h [1,128,512] fp32.
// Persistent kernel: 128 CTAs (4 batch-chunks x 32 j-slices), weights resident
// in SMEM, grid barrier per timestep, fp32x2-packed inner product.

#define BATCH 128
#define TT    512
#define II    256
#define HH    512
#define GB    4      // batch chunks
#define GJ    32     // j slices
#define BC    32     // batch per CTA
#define JC    16     // hidden cols per CTA
#define NCTA  (GB*GJ)   // 128
#define NTHR  256
#define USTRIDE 260     // 256 + 4 pad floats

#define SMEM_W   (48*768)
#define SMEM_U   (32*USTRIDE)
#define SMEM_FLOATS (SMEM_W + 2*SMEM_U + 64)
#define SMEM_BYTES  (SMEM_FLOATS*4)

__device__ float g_h[2][BATCH*HH];
__device__ unsigned int g_count = 0;
__device__ unsigned int g_phase = 0;

__device__ __forceinline__ void fma2(unsigned long long &d,
                                     unsigned long long a,
                                     unsigned long long b) {
    asm("fma.rn.f32x2 %0, %1, %2, %0;" : "+l"(d) : "l"(a), "l"(b));
}

__device__ __forceinline__ float foldadd(unsigned long long v) {
    float lo, hi;
    asm("mov.b64 {%0, %1}, %2;" : "=f"(lo), "=f"(hi) : "l"(v));
    return lo + hi;
}

__device__ __forceinline__ void grid_sync() {
    __syncthreads();
    if (threadIdx.x == 0) {
        __threadfence();
        unsigned gen = *((volatile unsigned*)&g_phase);
        if (atomicAdd(&g_count, 1u) == NCTA - 1u) {
            g_count = 0;
            __threadfence();
            *((volatile unsigned*)&g_phase) = gen + 1u;
        } else {
            while (*((volatile unsigned*)&g_phase) == gen) { __nanosleep(64); }
        }
        __threadfence();
    }
    __syncthreads();
}

extern "C" __global__ void __launch_bounds__(NTHR, 1)
gru_persistent_kernel(const float* __restrict__ x,      // [B, T, I]
                      const float* __restrict__ W_ih,   // [3H, I]
                      const float* __restrict__ W_hh,   // [3H, H]
                      const float* __restrict__ b_ih,   // [3H]
                      const float* __restrict__ b_hh,   // [3H]
                      float* __restrict__ out)          // [1, B, H]
{
    extern __shared__ float smem[];
    float* W_s  = smem;                 // [48][768] fused [W_ih | W_hh] rows
    float* U_s0 = W_s + SMEM_W;         // [32][USTRIDE]
    float* U_s1 = U_s0 + SMEM_U;        // [32][USTRIDE]
    float* B_s  = U_s1 + SMEM_U;        // [64] biases

    const int tid = threadIdx.x;
    const int bx  = blockIdx.x;
    const int gb  = bx & (GB - 1);
    const int gj  = bx >> 2;
    const int b0  = gb * BC;
    const int j0  = gj * JC;

    // ---- one-time: load fused weight tile into SMEM ----
    // local rows 0..15 = r (gate rows j0+i), 16..31 = z (512+j0+i), 32..47 = n (1024+j0+i)
    for (int idx = tid; idx < 48 * 768; idx += NTHR) {
        int row = idx / 768;
        int col = idx - row * 768;
        int G;
        if (row < 16)      G = j0 + row;
        else if (row < 32) G = 512 + j0 + (row - 16);
        else               G = 1024 + j0 + (row - 32);
        float v = (col < II) ? W_ih[G * II + col] : W_hh[G * HH + (col - II)];
        W_s[idx] = v;
    }
    if (tid < 64) {
        int i = tid & 15;
        float v;
        if (tid < 16)      v = b_ih[j0 + i]       + b_hh[j0 + i];        // r fused
        else if (tid < 32) v = b_ih[512 + j0 + i] + b_hh[512 + j0 + i];  // z fused
        else if (tid < 48) v = b_ih[1024 + j0 + i];                      // xn bias
        else               v = b_hh[1024 + j0 + i];                      // hn bias
        B_s[tid] = v;
    }

    // zero h0 (parity 0)
    for (int idx = bx * NTHR + tid; idx < BATCH * HH; idx += NCTA * NTHR)
        g_h[0][idx] = 0.0f;

    grid_sync();

    const int tg  = tid >> 4;     // 0..15 -> local j index
    const int tbp = tid & 15;     // 0..15 -> batch pair
    const int bl0 = tbp * 2;
    const int j   = j0 + tg;

    const int ldrow = tid >> 3;   // 0..31 local batch row for loads
    const int ldv   = tid & 7;    // vec4 lane within row

    const float bias_r  = B_s[tg];
    const float bias_z  = B_s[16 + tg];
    const float bias_xn = B_s[32 + tg];
    const float bias_hn = B_s[48 + tg];

    for (int t = 0; t < TT; t++) {
        const int rp = t & 1;
        const int wp = rp ^ 1;

        unsigned long long ar0 = 0ull, ar1 = 0ull;
        unsigned long long az0 = 0ull, az1 = 0ull;
        unsigned long long axn0 = 0ull, axn1 = 0ull;
        unsigned long long ahn0 = 0ull, ahn1 = 0ull;

        #pragma unroll
        for (int c = 0; c < 3; c++) {
            float* U = (c & 1) ? U_s1 : U_s0;

            // stage U chunk: chunk 0 = x_t slice, chunks 1,2 = h slices
            const float* src;
            if (c == 0) src = x + ((size_t)(b0 + ldrow) * TT + t) * II;
            else        src = g_h[rp] + (b0 + ldrow) * HH + (c - 1) * II;
            float4* dst = (float4*)(U + ldrow * USTRIDE);
            const float4* s4 = (const float4*)src;
            #pragma unroll
            for (int it = 0; it < 8; it++)
                dst[ldv + 8 * it] = s4[ldv + 8 * it];
            __syncthreads();

            // inner product, K-packed f32x2 (even/odd k lanes)
            const ulonglong2* wr = (const ulonglong2*)(W_s + tg * 768 + c * 256);
            const ulonglong2* wz = (const ulonglong2*)(W_s + (16 + tg) * 768 + c * 256);
            const ulonglong2* wn = (const ulonglong2*)(W_s + (32 + tg) * 768 + c * 256);
            const ulonglong2* u0 = (const ulonglong2*)(U + bl0 * USTRIDE);
            const ulonglong2* u1 = (const ulonglong2*)(U + (bl0 + 1) * USTRIDE);

            unsigned long long n0 = (c == 0) ? axn0 : ahn0;
            unsigned long long n1 = (c == 0) ? axn1 : ahn1;

            #pragma unroll 4
            for (int k4 = 0; k4 < 64; k4++) {
                ulonglong2 w_r = wr[k4];
                ulonglong2 w_z = wz[k4];
                ulonglong2 w_n = wn[k4];
                ulonglong2 ua  = u0[k4];
                ulonglong2 ub  = u1[k4];
                fma2(ar0, w_r.x, ua.x); fma2(az0, w_z.x, ua.x); fma2(n0, w_n.x, ua.x);
                fma2(ar1, w_r.x, ub.x); fma2(az1, w_z.x, ub.x); fma2(n1, w_n.x, ub.x);
                fma2(ar0, w_r.y, ua.y); fma2(az0, w_z.y, ua.y); fma2(n0, w_n.y, ua.y);
                fma2(ar1, w_r.y, ub.y); fma2(az1, w_z.y, ub.y); fma2(n1, w_n.y, ub.y);
            }
            if (c == 0) { axn0 = n0; axn1 = n1; }
            else        { ahn0 = n0; ahn1 = n1; }
        }

        // gate math + h update for the thread's (j, batch pair)
        float pr0 = foldadd(ar0) + bias_r;
        float pr1 = foldadd(ar1) + bias_r;
        float pz0 = foldadd(az0) + bias_z;
        float pz1 = foldadd(az1) + bias_z;
        float xn0 = foldadd(axn0) + bias_xn;
        float xn1 = foldadd(axn1) + bias_xn;
        float hn0 = foldadd(ahn0) + bias_hn;
        float hn1 = foldadd(ahn1) + bias_hn;

        float r0v = 1.0f / (1.0f + __expf(-pr0));
        float r1v = 1.0f / (1.0f + __expf(-pr1));
        float z0v = 1.0f / (1.0f + __expf(-pz0));
        float z1v = 1.0f / (1.0f + __expf(-pz1));
        float n0v = tanhf(xn0 + r0v * hn0);
        float n1v = tanhf(xn1 + r1v * hn1);

        // h_old is still staged in SMEM: chunk1(buf1)=h[0..255], chunk2(buf0)=h[256..511]
        const float* hbuf = (j < 256) ? U_s1 : U_s0;
        const int hcol = j & 255;
        float h0 = hbuf[bl0 * USTRIDE + hcol];
        float h1 = hbuf[(bl0 + 1) * USTRIDE + hcol];

        float hnew0 = n0v + z0v * (h0 - n0v);
        float hnew1 = n1v + z1v * (h1 - n1v);

        const int bg = b0 + bl0;
        g_h[wp][bg * HH + j]       = hnew0;
        g_h[wp][(bg + 1) * HH + j] = hnew1;
        if (t == TT - 1) {
            out[bg * HH + j]       = hnew0;
            out[(bg + 1) * HH + j] = hnew1;
        }

        grid_sync();
    }
}

extern "C" void kernel_launch(void* const* d_in, const int* in_sizes, int n_in,
                              void* d_out, int out_size) {
    (void)in_sizes; (void)n_in; (void)out_size;
    cudaFuncSetAttribute(gru_persistent_kernel,
                         cudaFuncAttributeMaxDynamicSharedMemorySize, SMEM_BYTES);
    gru_persistent_kernel<<<NCTA, NTHR, SMEM_BYTES>>>(
        (const float*)d_in[0],   // encoder_inputs [128,512,256]
        (const float*)d_in[1],   // W_ih [1536,256]
        (const float*)d_in[2],   // W_hh [1536,512]
        (const float*)d_in[3],   // b_ih [1536]
        (const float*)d_in[4],   // b_hh [1536]
        (float*)d_out);          // [1,128,512]
}

// round 3
// speedup vs baseline: 1.2682x; 1.2682x over previous
#include <cuda_runtime.h>
#include <math.h>

// GRU: B=128, T=512, I=256, H=512. out = final h [1,128,512] fp32.
// Persistent kernel, 128 CTAs (4 batch-chunks x 32 j-slices), weights in SMEM.
// Register-tiled inner product: each thread = 2j x 4b x 3 gates, K split 4-way
// across lanes, f32x2-packed FMAs, shfl reduction.

#define BATCH 128
#define TT    512
#define II    256
#define HH    512
#define GB    4
#define GJ    32
#define BC    32
#define JC    16
#define NCTA  (GB*GJ)
#define NTHR  256
#define USTRIDE 260          // 256 + 4 pad (stride % 32 banks == 4)
#define WSTRIDE 772          // 768 + 4 pad

#define SMEM_W   (48*WSTRIDE)
#define SMEM_U   (32*USTRIDE)
#define SMEM_FLOATS (SMEM_W + 2*SMEM_U + 64)
#define SMEM_BYTES  (SMEM_FLOATS*4)

typedef unsigned long long ull;

__device__ float g_h[2][BATCH*HH];
__device__ unsigned int g_count = 0;
__device__ unsigned int g_phase = 0;

__device__ __forceinline__ void fma2(ull &d, ull a, ull b) {
    asm("fma.rn.f32x2 %0, %1, %2, %0;" : "+l"(d) : "l"(a), "l"(b));
}
__device__ __forceinline__ float foldadd(ull v) {
    float lo, hi;
    asm("mov.b64 {%0, %1}, %2;" : "=f"(lo), "=f"(hi) : "l"(v));
    return lo + hi;
}
__device__ __forceinline__ float red4(float v) {
    v += __shfl_xor_sync(0xFFFFFFFFu, v, 1);
    v += __shfl_xor_sync(0xFFFFFFFFu, v, 2);
    return v;
}
__device__ __forceinline__ float sigm(float x) {
    return 1.0f / (1.0f + __expf(-x));
}

__device__ __forceinline__ void grid_sync() {
    __syncthreads();
    if (threadIdx.x == 0) {
        __threadfence();
        unsigned gen = *((volatile unsigned*)&g_phase);
        if (atomicAdd(&g_count, 1u) == NCTA - 1u) {
            g_count = 0;
            __threadfence();
            *((volatile unsigned*)&g_phase) = gen + 1u;
        } else {
            while (*((volatile unsigned*)&g_phase) == gen) { __nanosleep(64); }
        }
        __threadfence();
    }
    __syncthreads();
}

extern "C" __global__ void __launch_bounds__(NTHR, 1)
gru_persistent_kernel(const float* __restrict__ x,      // [B, T, I]
                      const float* __restrict__ W_ih,   // [3H, I]
                      const float* __restrict__ W_hh,   // [3H, H]
                      const float* __restrict__ b_ih,   // [3H]
                      const float* __restrict__ b_hh,   // [3H]
                      float* __restrict__ out)          // [1, B, H]
{
    extern __shared__ float smem[];
    float* W_s  = smem;                 // [48][WSTRIDE] fused [W_ih | W_hh]
    float* U_s0 = W_s + SMEM_W;         // [32][USTRIDE]
    float* U_s1 = U_s0 + SMEM_U;
    float* B_s  = U_s1 + SMEM_U;        // [64]

    const int tid = threadIdx.x;
    const int bx  = blockIdx.x;
    const int gb  = bx & (GB - 1);
    const int gj  = bx >> 2;
    const int b0  = gb * BC;
    const int j0  = gj * JC;

    // ---- one-time: weight tile into SMEM (rows 0-15 r, 16-31 z, 32-47 n) ----
    for (int idx = tid; idx < 48 * 768; idx += NTHR) {
        int row = idx / 768;
        int col = idx - row * 768;
        int G;
        if (row < 16)      G = j0 + row;
        else if (row < 32) G = 512 + j0 + (row - 16);
        else               G = 1024 + j0 + (row - 32);
        float v = (col < II) ? W_ih[G * II + col] : W_hh[G * HH + (col - II)];
        W_s[row * WSTRIDE + col] = v;
    }
    if (tid < 64) {
        int i = tid & 15;
        float v;
        if (tid < 16)      v = b_ih[j0 + i]       + b_hh[j0 + i];        // r
        else if (tid < 32) v = b_ih[512 + j0 + i] + b_hh[512 + j0 + i];  // z
        else if (tid < 48) v = b_ih[1024 + j0 + i];                      // xn
        else               v = b_hh[1024 + j0 + i];                      // hn
        B_s[tid] = v;
    }

    for (int idx = bx * NTHR + tid; idx < BATCH * HH; idx += NCTA * NTHR)
        g_h[0][idx] = 0.0f;

    grid_sync();

    // thread mapping: s = k-slice lane, bslot = batch slot, jp = j-pair (warp)
    const int s     = tid & 3;
    const int bslot = (tid >> 2) & 7;
    const int jp    = tid >> 5;          // 0..7

    const int ldrow = tid >> 3;          // staging
    const int ldv   = tid & 7;

    // biases for this thread's j-pair
    const float br_[2]  = { B_s[2*jp],      B_s[2*jp + 1] };
    const float bz_[2]  = { B_s[16 + 2*jp], B_s[16 + 2*jp + 1] };
    const float bxn_[2] = { B_s[32 + 2*jp], B_s[32 + 2*jp + 1] };
    const float bhn_[2] = { B_s[48 + 2*jp], B_s[48 + 2*jp + 1] };

    for (int t = 0; t < TT; t++) {
        const int rp = t & 1;
        const int wp = rp ^ 1;

        ull ar[2][4], az[2][4], an[2][4];
        float xn[2][4];
        #pragma unroll
        for (int jj = 0; jj < 2; jj++)
            #pragma unroll
            for (int q = 0; q < 4; q++) { ar[jj][q] = 0; az[jj][q] = 0; an[jj][q] = 0; }

        #pragma unroll
        for (int c = 0; c < 3; c++) {
            float* U = (c & 1) ? U_s1 : U_s0;

            // stage U chunk: c==0 -> x_t slice, c==1/2 -> h halves
            const float* src = (c == 0)
                ? x + ((size_t)(b0 + ldrow) * TT + t) * II
                : g_h[rp] + (b0 + ldrow) * HH + (c - 1) * II;
            float4* dst = (float4*)(U + ldrow * USTRIDE);
            const float4* s4 = (const float4*)src;
            #pragma unroll
            for (int it = 0; it < 8; it++)
                dst[ldv + 8 * it] = s4[ldv + 8 * it];
            __syncthreads();

            const ulonglong2* w_r0 = (const ulonglong2*)(W_s + (2*jp+0)*WSTRIDE + c*256) + s;
            const ulonglong2* w_r1 = (const ulonglong2*)(W_s + (2*jp+1)*WSTRIDE + c*256) + s;
            const ulonglong2* w_z0 = (const ulonglong2*)(W_s + (16+2*jp+0)*WSTRIDE + c*256) + s;
            const ulonglong2* w_z1 = (const ulonglong2*)(W_s + (16+2*jp+1)*WSTRIDE + c*256) + s;
            const ulonglong2* w_n0 = (const ulonglong2*)(W_s + (32+2*jp+0)*WSTRIDE + c*256) + s;
            const ulonglong2* w_n1 = (const ulonglong2*)(W_s + (32+2*jp+1)*WSTRIDE + c*256) + s;
            const ulonglong2* u_0  = (const ulonglong2*)(U + (bslot+ 0)*USTRIDE) + s;
            const ulonglong2* u_1  = (const ulonglong2*)(U + (bslot+ 8)*USTRIDE) + s;
            const ulonglong2* u_2  = (const ulonglong2*)(U + (bslot+16)*USTRIDE) + s;
            const ulonglong2* u_3  = (const ulonglong2*)(U + (bslot+24)*USTRIDE) + s;

            for (int i = 0; i < 16; i++) {
                const int idx = 4 * i;
                ulonglong2 Wv[3][2];
                Wv[0][0] = w_r0[idx]; Wv[0][1] = w_r1[idx];
                Wv[1][0] = w_z0[idx]; Wv[1][1] = w_z1[idx];
                Wv[2][0] = w_n0[idx]; Wv[2][1] = w_n1[idx];
                ulonglong2 Uv[4];
                Uv[0] = u_0[idx]; Uv[1] = u_1[idx]; Uv[2] = u_2[idx]; Uv[3] = u_3[idx];

                #pragma unroll
                for (int jj = 0; jj < 2; jj++)
                    #pragma unroll
                    for (int q = 0; q < 4; q++) {
                        fma2(ar[jj][q], Wv[0][jj].x, Uv[q].x);
                        fma2(ar[jj][q], Wv[0][jj].y, Uv[q].y);
                        fma2(az[jj][q], Wv[1][jj].x, Uv[q].x);
                        fma2(az[jj][q], Wv[1][jj].y, Uv[q].y);
                        fma2(an[jj][q], Wv[2][jj].x, Uv[q].x);
                        fma2(an[jj][q], Wv[2][jj].y, Uv[q].y);
                    }
            }

            if (c == 0) {
                #pragma unroll
                for (int jj = 0; jj < 2; jj++)
                    #pragma unroll
                    for (int q = 0; q < 4; q++) {
                        xn[jj][q] = foldadd(an[jj][q]);
                        an[jj][q] = 0;
                    }
            }
        }

        // fold f32x2 + reduce across the 4 k-slice lanes
        float vr[2][4], vz[2][4], vh[2][4];
        #pragma unroll
        for (int jj = 0; jj < 2; jj++)
            #pragma unroll
            for (int q = 0; q < 4; q++) {
                vr[jj][q] = red4(foldadd(ar[jj][q]));
                vz[jj][q] = red4(foldadd(az[jj][q]));
                vh[jj][q] = red4(foldadd(an[jj][q]));
                xn[jj][q] = red4(xn[jj][q]);
            }

        if (s == 0) {
            #pragma unroll
            for (int q = 0; q < 4; q++) {
                const int b_local = bslot + 8 * q;
                const int bg = b0 + b_local;
                float2 hnew;
                #pragma unroll
                for (int jj = 0; jj < 2; jj++) {
                    const int j = j0 + 2 * jp + jj;
                    float r = sigm(vr[jj][q] + br_[jj]);
                    float z = sigm(vz[jj][q] + bz_[jj]);
                    float n = tanhf(xn[jj][q] + bxn_[jj] + r * (vh[jj][q] + bhn_[jj]));
                    // h_old still staged: chunk1 (U_s1) = h[0:256], chunk2 (U_s0) = h[256:512]
                    const float* hbuf = (j < 256) ? U_s1 : U_s0;
                    float hold = hbuf[b_local * USTRIDE + (j & 255)];
                    float hv = n + z * (hold - n);
                    if (jj == 0) hnew.x = hv; else hnew.y = hv;
                }
                *(float2*)(g_h[wp] + bg * HH + j0 + 2 * jp) = hnew;
                if (t == TT - 1)
                    *(float2*)(out + bg * HH + j0 + 2 * jp) = hnew;
            }
        }

        grid_sync();
    }
}

extern "C" void kernel_launch(void* const* d_in, const int* in_sizes, int n_in,
                              void* d_out, int out_size) {
    (void)in_sizes; (void)n_in; (void)out_size;
    cudaFuncSetAttribute(gru_persistent_kernel,
                         cudaFuncAttributeMaxDynamicSharedMemorySize, SMEM_BYTES);
    gru_persistent_kernel<<<NCTA, NTHR, SMEM_BYTES>>>(
        (const float*)d_in[0],
        (const float*)d_in[1],
        (const float*)d_in[2],
        (const float*)d_in[3],
        (const float*)d_in[4],
        (float*)d_out);
}